// round 6
// baseline (speedup 1.0000x reference)
#include <cuda_runtime.h>
#include <math.h>

#define EPSF 1e-8f
#define BATCH 16

// ---------------- scratch (device globals; no allocation allowed) ----------------
__device__ float g_dm4[2][BATCH][128 * 128];   // block-4 sums (p=0, g=1)
__device__ float g_cvh[2][BATCH][128 * 128];   // horizontal gaussian pass
__device__ float g_cvv[2][BATCH][128 * 128];   // vertical gaussian pass (smoothed)
__device__ float g_ot8[2][BATCH][64 * 64];     // block-8 sums
__device__ float g_sums[2][BATCH];             // per-batch totals
__device__ float g_vpart[2][BATCH][4];         // per-chunk sums of smoothed field
__device__ float g_dmpart[BATCH][4];           // per-chunk kl+l2 partials
__device__ float g_ot_pb[BATCH];               // per-batch masked OT cost

// ---------------- helpers ----------------
__device__ __forceinline__ float block_reduce(float v, float* scratch)
{
    int tid = threadIdx.x + threadIdx.y * blockDim.x;
    unsigned m = 0xffffffffu;
#pragma unroll
    for (int o = 16; o > 0; o >>= 1) v += __shfl_down_sync(m, v, o);
    int lane = tid & 31, w = tid >> 5;
    int nw = (blockDim.x * blockDim.y + 31) >> 5;
    if (lane == 0) scratch[w] = v;
    __syncthreads();
    v = (tid < nw) ? scratch[tid] : 0.f;
    __syncthreads();
    if (w == 0) {
#pragma unroll
        for (int o = 16; o > 0; o >>= 1) v += __shfl_down_sync(m, v, o);
    }
    return v;  // valid in thread 0
}

__device__ __forceinline__ void make_gauss(float* gk, float* ginv, int tid, int nthreads)
{
    if (tid < 49) {
        float d = (float)tid - 24.f;
        gk[tid] = expf(-(d * d) * (1.f / 128.f));
    }
    __syncthreads();
    if (tid == 0) {
        float s = 0.f;
        for (int i = 0; i < 49; ++i) s += gk[i];
        *ginv = 1.f / s;
    }
    __syncthreads();
}

// ---------------- kernel 1: 4x4 block sums (memory bound: 32 MB read) ----------------
__global__ void __launch_bounds__(256) k_blocksum4(const float* __restrict__ pred,
                                                   const float* __restrict__ gt)
{
    int z = blockIdx.z;
    int arr = z >> 4, b = z & 15;
    const float* in = (arr ? gt : pred) + (size_t)b * 512 * 512;
    int x = blockIdx.x * blockDim.x + threadIdx.x;  // 0..127
    int y = blockIdx.y * blockDim.y + threadIdx.y;  // 0..127
    float s = 0.f;
#pragma unroll
    for (int r = 0; r < 4; ++r) {
        float4 v = *reinterpret_cast<const float4*>(in + (size_t)(4 * y + r) * 512 + 4 * x);
        s += v.x + v.y + v.z + v.w;
    }
    g_dm4[arr][b][y * 128 + x] = s;
}

// ---------------- kernel 2: 8x8 block sums (=2x2 of dm4) + per-batch totals ----------------
__global__ void __launch_bounds__(1024) k_ot8_sums()
{
    __shared__ float scratch[32];
    int arr = blockIdx.x >> 4, b = blockIdx.x & 15;
    const float* dm = g_dm4[arr][b];
    float* ot = g_ot8[arr][b];
    int tid = threadIdx.x;
    float loc = 0.f;
    for (int i = tid; i < 4096; i += 1024) {
        int y = i >> 6, x = i & 63;
        const float* p = dm + (2 * y) * 128 + 2 * x;
        float s = p[0] + p[1] + p[128] + p[129];
        ot[i] = s;
        loc += s;
    }
    float tot = block_reduce(loc, scratch);
    if (tid == 0) g_sums[arr][b] = tot;
}

// ---------------- kernel 3: horizontal 49-tap gaussian, 16 outputs/thread ----------------
// Lanes = rows (pitch 177 => odd mod 32 => conflict-free strided access); warp = x-group.
__global__ void __launch_bounds__(256) k_convh()
{
    __shared__ float s[32][177];   // cols [24,152) hold data, rest zero pad
    __shared__ float gk[49];
    __shared__ float ginv;
    int img = blockIdx.y;
    int arr = img >> 4, bb = img & 15;
    int rowbase = blockIdx.x * 32;
    int tid = threadIdx.x;  // 256
    const float* in = g_dm4[arr][bb];
    float* out = g_cvh[arr][bb];
    make_gauss(gk, &ginv, tid, 256);
    for (int i = tid; i < 32 * 177; i += 256) (&s[0][0])[i] = 0.f;
    __syncthreads();
    for (int i = tid; i < 32 * 128; i += 256) {
        int r = i >> 7, c = i & 127;
        s[r][c + 24] = in[(rowbase + r) * 128 + c];
    }
    __syncthreads();
    int lane = tid & 31;          // row within chunk
    int x0 = (tid >> 5) * 16;     // warp -> 16-wide x group
    const float* srow = &s[lane][x0];
    float acc[16];
#pragma unroll
    for (int k = 0; k < 16; ++k) acc[k] = 0.f;
#pragma unroll
    for (int j = 0; j < 49; ++j) {
        float wj = gk[j];
#pragma unroll
        for (int k = 0; k < 16; ++k) acc[k] = fmaf(wj, srow[j + k], acc[k]);
    }
    float gi = ginv;
    float* op = out + (rowbase + lane) * 128 + x0;
#pragma unroll
    for (int k = 0; k < 16; k += 4) {
        float4 v = make_float4(acc[k] * gi, acc[k + 1] * gi, acc[k + 2] * gi, acc[k + 3] * gi);
        *reinterpret_cast<float4*>(op + k) = v;
    }
}

// ---------------- kernel 4: vertical 49-tap gaussian, 16 outputs/thread + partial sums ----
__global__ void __launch_bounds__(256) k_convv()
{
    __shared__ float s[80 * 128];
    __shared__ float gk[49];
    __shared__ float ginv;
    __shared__ float red[32];
    int img = blockIdx.y;
    int arr = img >> 4, bb = img & 15;
    int ybase = blockIdx.x * 32;
    int tid = threadIdx.x;  // 256
    const float* in = g_cvh[arr][bb];
    float* out = g_cvv[arr][bb];
    make_gauss(gk, &ginv, tid, 256);
    for (int i = tid; i < 80 * 128; i += 256) {
        int r = i >> 7, x = i & 127;
        int sy = ybase - 24 + r;
        s[i] = (sy >= 0 && sy < 128) ? in[sy * 128 + x] : 0.f;
    }
    __syncthreads();
    int x = tid & 127;
    int yo = (tid >> 7) * 16;  // 0 or 16: local output base
    float acc[16];
#pragma unroll
    for (int k = 0; k < 16; ++k) acc[k] = 0.f;
#pragma unroll
    for (int j = 0; j < 49; ++j) {
        float wj = gk[j];
        const float* col = &s[(yo + j) * 128 + x];
#pragma unroll
        for (int k = 0; k < 16; ++k) acc[k] = fmaf(wj, col[k * 128], acc[k]);
    }
    float gi = ginv;
    float loc = 0.f;
#pragma unroll
    for (int k = 0; k < 16; ++k) {
        float v = acc[k] * gi;
        out[(ybase + yo + k) * 128 + x] = v;
        loc += v;
    }
    float tot = block_reduce(loc, red);
    if (tid == 0) g_vpart[arr][bb][blockIdx.x] = tot;
}

// ---------------- kernel 5: DM KL + L2 (single pass, 64 blocks) ----------------
__global__ void __launch_bounds__(1024) k_dmloss()
{
    __shared__ float red[32];
    int chunk = blockIdx.x, b = blockIdx.y;
    int tid = threadIdx.x;
    float sp = g_vpart[0][b][0] + g_vpart[0][b][1] + g_vpart[0][b][2] + g_vpart[0][b][3];
    float sg = g_vpart[1][b][0] + g_vpart[1][b][1] + g_vpart[1][b][2] + g_vpart[1][b][3];
    float ip = 1.f / fmaxf(sp, EPSF);
    float ig = 1.f / fmaxf(sg, EPSF);
    const float* ps = g_cvv[0][b] + chunk * 4096;
    const float* gs = g_cvv[1][b] + chunk * 4096;
    float acc = 0.f;
    for (int i = tid; i < 4096; i += 1024) {
        float pn = ps[i] * ip, gn = gs[i] * ig;
        float kl = gn * logf((gn + EPSF) / (pn + EPSF));
        float d = pn - gn;
        acc += kl + d * d;
    }
    float tot = block_reduce(acc, red);
    if (tid == 0) g_dmpart[b][chunk] = tot;
}

// ---------------- kernel 6: Sinkhorn (exact-in-f32 3x3 stencil form of K) ----------------
// Unchanged from the passing round-5 version (known-good).
__device__ __forceinline__ void conv_rows(const float* E, const float* O, int eb, float w1,
                                          float& t00, float& t01, float& t10, float& t11)
{
    float ra[4], rb[4];
#pragma unroll
    for (int r = 0; r < 4; ++r) {
        float e0 = E[eb + r * 34], e1 = E[eb + r * 34 + 1];
        float o0 = O[eb + r * 34], o1 = O[eb + r * 34 + 1];
        ra[r] = fmaf(w1, o0 + o1, e0);  // row-sum for even-x output
        rb[r] = fmaf(w1, e0 + e1, o1);  // row-sum for odd-x output
    }
    t00 = fmaf(w1, ra[0] + ra[2], ra[1]);
    t10 = fmaf(w1, ra[1] + ra[3], ra[2]);
    t01 = fmaf(w1, rb[0] + rb[2], rb[1]);
    t11 = fmaf(w1, rb[1] + rb[3], rb[2]);
}

__global__ void __launch_bounds__(1024) k_sinkhorn()
{
    __shared__ float UE[66 * 34], UO[66 * 34], VE[66 * 34], VO[66 * 34];
    __shared__ float red[32];
    int b = blockIdx.x;
    int tx = threadIdx.x, ty = threadIdx.y;
    int tid = ty * 32 + tx;

    for (int i = tid; i < 66 * 34; i += 1024) { UE[i] = 0.f; UO[i] = 0.f; VE[i] = 0.f; VO[i] = 0.f; }
    __syncthreads();

    int y0 = 2 * ty, x0 = 2 * tx;
    int eb = y0 * 34 + tx;  // plane row y0 (= field row y0-1), col tx

    // u = ones (interior only; halo stays 0)
    UE[eb + 34] = 1.f; UO[eb + 35] = 1.f;
    UE[eb + 68] = 1.f; UO[eb + 69] = 1.f;

    const float w1 = expf(-1.f / 0.1f);   // dist^2 = 1
    const float w2 = expf(-2.f / 0.1f);   // dist^2 = 2
    float asum = fmaxf(g_sums[0][b], EPSF);
    float bsum = fmaxf(g_sums[1][b], EPSF);
    const float* pa = g_ot8[0][b];
    const float* pb = g_ot8[1][b];
    int i00 = y0 * 64 + x0;
    float a00 = pa[i00] / asum, a01 = pa[i00 + 1] / asum;
    float a10 = pa[i00 + 64] / asum, a11 = pa[i00 + 65] / asum;
    float b00 = pb[i00] / bsum, b01 = pb[i00 + 1] / bsum;
    float b10 = pb[i00 + 64] / bsum, b11 = pb[i00 + 65] / bsum;

    float v00, v01, v10, v11;
    __syncthreads();

    for (int it = 0; it < 50; ++it) {
        float t00, t01, t10, t11;
        conv_rows(UE, UO, eb, w1, t00, t01, t10, t11);       // K @ u
        v00 = __fdividef(b00, t00 + EPSF);
        v01 = __fdividef(b01, t01 + EPSF);
        v10 = __fdividef(b10, t10 + EPSF);
        v11 = __fdividef(b11, t11 + EPSF);
        VE[eb + 34] = v00; VO[eb + 35] = v01;
        VE[eb + 68] = v10; VO[eb + 69] = v11;
        __syncthreads();
        conv_rows(VE, VO, eb, w1, t00, t01, t10, t11);       // K @ v
        UE[eb + 34] = __fdividef(a00, t00 + EPSF);
        UO[eb + 35] = __fdividef(a01, t01 + EPSF);
        UE[eb + 68] = __fdividef(a10, t10 + EPSF);
        UO[eb + 69] = __fdividef(a11, t11 + EPSF);
        __syncthreads();
    }

    // cost = sum_j v_j * ( w1 * sum_{d2=1} u_i + 2*w2 * sum_{d2=2} u_i )  (diagonal C=0)
    float c = 0.f;
    {   // (y0, x0) even-x, plane row y0+1
        float s1 = UE[eb] + UE[eb + 68] + UO[eb + 34] + UO[eb + 35];
        float s2 = UO[eb] + UO[eb + 1] + UO[eb + 68] + UO[eb + 69];
        c += v00 * fmaf(w1, s1, 2.f * w2 * s2);
    }
    {   // (y0, x0+1) odd-x
        float s1 = UO[eb + 1] + UO[eb + 69] + UE[eb + 34] + UE[eb + 35];
        float s2 = UE[eb] + UE[eb + 1] + UE[eb + 68] + UE[eb + 69];
        c += v01 * fmaf(w1, s1, 2.f * w2 * s2);
    }
    {   // (y0+1, x0), plane row y0+2
        float s1 = UE[eb + 34] + UE[eb + 102] + UO[eb + 68] + UO[eb + 69];
        float s2 = UO[eb + 34] + UO[eb + 35] + UO[eb + 102] + UO[eb + 103];
        c += v10 * fmaf(w1, s1, 2.f * w2 * s2);
    }
    {   // (y0+1, x0+1)
        float s1 = UO[eb + 35] + UO[eb + 103] + UE[eb + 68] + UE[eb + 69];
        float s2 = UE[eb + 34] + UE[eb + 35] + UE[eb + 102] + UE[eb + 103];
        c += v11 * fmaf(w1, s1, 2.f * w2 * s2);
    }
    float tot = block_reduce(c, red);
    if (tid == 0) {
        bool mask = (asum > 0.5f) && (bsum > 0.5f);
        g_ot_pb[b] = mask ? tot : 0.f;
    }
}

// ---------------- kernel 7: final scalar (single writer -> deterministic) ----------------
__global__ void __launch_bounds__(32) k_final(const int* __restrict__ gt_counts,
                                              const int* __restrict__ cell_area,
                                              float* __restrict__ out)
{
    int lane = threadIdx.x;
    float cl = 0.f, dm = 0.f, ot = 0.f;
    if (lane < BATCH) {
        int craw = cell_area[0];
        // robust to int32 or float32 encoding of the scalar (both yield 1.0 here)
        float ca = (craw >= 1 && craw <= 1000000) ? (float)craw : __int_as_float(craw);
        float pc = fmaxf(g_sums[0][lane] / ca, 0.f);
        float d = fabsf(pc - (float)gt_counts[lane]);
        cl = (d < 10.f) ? (0.5f * d * d / 10.f) : (d - 5.f);
        dm = g_dmpart[lane][0] + g_dmpart[lane][1] + g_dmpart[lane][2] + g_dmpart[lane][3];
        ot = g_ot_pb[lane];
    }
#pragma unroll
    for (int o = 16; o > 0; o >>= 1) {
        cl += __shfl_down_sync(0xffffffffu, cl, o);
        dm += __shfl_down_sync(0xffffffffu, dm, o);
        ot += __shfl_down_sync(0xffffffffu, ot, o);
    }
    if (lane == 0)
        out[0] = 3.0f * (cl * (1.f / 16.f)) + 0.5f * (dm * (1.f / 16.f)) + 0.3f * (ot * (1.f / 16.f));
}

// ---------------- launch ----------------
extern "C" void kernel_launch(void* const* d_in, const int* in_sizes, int n_in,
                              void* d_out, int out_size)
{
    const float* pred = (const float*)d_in[0];
    const float* gt = (const float*)d_in[1];
    const int* counts = (const int*)d_in[2];
    const int* cell = (const int*)d_in[3];
    float* out = (float*)d_out;

    k_blocksum4<<<dim3(4, 16, 32), dim3(32, 8)>>>(pred, gt);
    k_ot8_sums<<<32, 1024>>>();
    k_convh<<<dim3(4, 32), 256>>>();
    k_convv<<<dim3(4, 32), 256>>>();
    k_dmloss<<<dim3(4, 16), 1024>>>();
    k_sinkhorn<<<16, dim3(32, 32)>>>();
    k_final<<<1, 32>>>(counts, cell, out);
}

// round 7
// speedup vs baseline: 1.9278x; 1.9278x over previous
#include <cuda_runtime.h>
#include <math.h>

#define EPSF 1e-8f
#define BATCH 16

// ---------------- scratch (device globals; no allocation allowed) ----------------
__device__ float g_dm4[2][BATCH][128 * 128];   // block-4 sums (p=0, g=1)
__device__ float g_cvh[2][BATCH][128 * 128];   // horizontal gaussian pass
__device__ float g_cvv[2][BATCH][128 * 128];   // vertical gaussian pass (smoothed)
__device__ float g_ot8[2][BATCH][64 * 64];     // block-8 sums
__device__ float g_spart[2][BATCH][64];        // per-block partial sums of density
__device__ float g_sums[2][BATCH];             // per-batch totals (written by sinkhorn)
__device__ float g_vpart[2][BATCH][4];         // per-chunk sums of smoothed field
__device__ float g_dmpart[BATCH][4];           // per-chunk kl+l2 partials
__device__ float g_ot_pb[BATCH];               // per-batch masked OT cost

// ---------------- helpers ----------------
__device__ __forceinline__ float block_reduce(float v, float* scratch)
{
    int tid = threadIdx.x + threadIdx.y * blockDim.x;
    unsigned m = 0xffffffffu;
#pragma unroll
    for (int o = 16; o > 0; o >>= 1) v += __shfl_down_sync(m, v, o);
    int lane = tid & 31, w = tid >> 5;
    int nw = (blockDim.x * blockDim.y + 31) >> 5;
    if (lane == 0) scratch[w] = v;
    __syncthreads();
    v = (tid < nw) ? scratch[tid] : 0.f;
    __syncthreads();
    if (w == 0) {
#pragma unroll
        for (int o = 16; o > 0; o >>= 1) v += __shfl_down_sync(m, v, o);
    }
    return v;  // valid in thread 0
}

__device__ __forceinline__ void make_gauss(float* gk, float* ginv, int tid)
{
    if (tid < 49) {
        float d = (float)tid - 24.f;
        gk[tid] = expf(-(d * d) * (1.f / 128.f));
    }
    __syncthreads();
    if (tid == 0) {
        float s = 0.f;
        for (int i = 0; i < 49; ++i) s += gk[i];
        *ginv = 1.f / s;
    }
    __syncthreads();
}

// ---- kernel 1: 4x4 block sums + fused 8x8 ot cells + per-block partial sums ----
__global__ void __launch_bounds__(256) k_blocksum4(const float* __restrict__ pred,
                                                   const float* __restrict__ gt)
{
    __shared__ float sm[8][33];
    __shared__ float red[32];
    int z = blockIdx.z;
    int arr = z >> 4, b = z & 15;
    const float* in = (arr ? gt : pred) + (size_t)b * 512 * 512;
    int tx = threadIdx.x, ty = threadIdx.y;
    int x = blockIdx.x * 32 + tx;   // dm4 col 0..127
    int y = blockIdx.y * 8 + ty;    // dm4 row 0..127
    float s = 0.f;
#pragma unroll
    for (int r = 0; r < 4; ++r) {
        float4 v = *reinterpret_cast<const float4*>(in + (size_t)(4 * y + r) * 512 + 4 * x);
        s += v.x + v.y + v.z + v.w;
    }
    g_dm4[arr][b][y * 128 + x] = s;
    sm[ty][tx] = s;
    float tot = block_reduce(s, red);   // contains syncs -> sm visible after
    int tid = ty * 32 + tx;
    if (tid == 0) g_spart[arr][b][blockIdx.y * 4 + blockIdx.x] = tot;
    if (tid < 64) {
        int r = tid >> 4, cc = tid & 15;
        float v = sm[2 * r][2 * cc] + sm[2 * r][2 * cc + 1] +
                  sm[2 * r + 1][2 * cc] + sm[2 * r + 1][2 * cc + 1];
        g_ot8[arr][b][(blockIdx.y * 4 + r) * 64 + blockIdx.x * 16 + cc] = v;
    }
}

// ---------------- kernel 2: horizontal 49-tap gaussian, 16 outputs/thread ----------------
__global__ void __launch_bounds__(256) k_convh()
{
    __shared__ float s[32][177];   // cols [24,152) hold data, rest zero pad
    __shared__ float gk[49];
    __shared__ float ginv;
    int img = blockIdx.y;
    int arr = img >> 4, bb = img & 15;
    int rowbase = blockIdx.x * 32;
    int tid = threadIdx.x;  // 256
    const float* in = g_dm4[arr][bb];
    float* out = g_cvh[arr][bb];
    make_gauss(gk, &ginv, tid);
    for (int i = tid; i < 32 * 177; i += 256) (&s[0][0])[i] = 0.f;
    __syncthreads();
    for (int i = tid; i < 32 * 128; i += 256) {
        int r = i >> 7, c = i & 127;
        s[r][c + 24] = in[(rowbase + r) * 128 + c];
    }
    __syncthreads();
    int lane = tid & 31;          // row within chunk
    int x0 = (tid >> 5) * 16;     // warp -> 16-wide x group
    const float* srow = &s[lane][x0];
    float acc[16];
#pragma unroll
    for (int k = 0; k < 16; ++k) acc[k] = 0.f;
#pragma unroll
    for (int j = 0; j < 49; ++j) {
        float wj = gk[j];
#pragma unroll
        for (int k = 0; k < 16; ++k) acc[k] = fmaf(wj, srow[j + k], acc[k]);
    }
    float gi = ginv;
    float* op = out + (rowbase + lane) * 128 + x0;
#pragma unroll
    for (int k = 0; k < 16; k += 4) {
        float4 v = make_float4(acc[k] * gi, acc[k + 1] * gi, acc[k + 2] * gi, acc[k + 3] * gi);
        *reinterpret_cast<float4*>(op + k) = v;
    }
}

// ---------------- kernel 3: vertical 49-tap gaussian, 16 outputs/thread + partial sums ----
__global__ void __launch_bounds__(256) k_convv()
{
    __shared__ float s[80 * 128];
    __shared__ float gk[49];
    __shared__ float ginv;
    __shared__ float red[32];
    int img = blockIdx.y;
    int arr = img >> 4, bb = img & 15;
    int ybase = blockIdx.x * 32;
    int tid = threadIdx.x;  // 256
    const float* in = g_cvh[arr][bb];
    float* out = g_cvv[arr][bb];
    make_gauss(gk, &ginv, tid);
    for (int i = tid; i < 80 * 128; i += 256) {
        int r = i >> 7, x = i & 127;
        int sy = ybase - 24 + r;
        s[i] = (sy >= 0 && sy < 128) ? in[sy * 128 + x] : 0.f;
    }
    __syncthreads();
    int x = tid & 127;
    int yo = (tid >> 7) * 16;  // 0 or 16: local output base
    float acc[16];
#pragma unroll
    for (int k = 0; k < 16; ++k) acc[k] = 0.f;
#pragma unroll
    for (int j = 0; j < 49; ++j) {
        float wj = gk[j];
        const float* col = &s[(yo + j) * 128 + x];
#pragma unroll
        for (int k = 0; k < 16; ++k) acc[k] = fmaf(wj, col[k * 128], acc[k]);
    }
    float gi = ginv;
    float loc = 0.f;
#pragma unroll
    for (int k = 0; k < 16; ++k) {
        float v = acc[k] * gi;
        out[(ybase + yo + k) * 128 + x] = v;
        loc += v;
    }
    float tot = block_reduce(loc, red);
    if (tid == 0) g_vpart[arr][bb][blockIdx.x] = tot;
}

// ---------------- kernel 4: DM KL + L2 (single pass, 64 blocks) ----------------
__global__ void __launch_bounds__(1024) k_dmloss()
{
    __shared__ float red[32];
    int chunk = blockIdx.x, b = blockIdx.y;
    int tid = threadIdx.x;
    float sp = g_vpart[0][b][0] + g_vpart[0][b][1] + g_vpart[0][b][2] + g_vpart[0][b][3];
    float sg = g_vpart[1][b][0] + g_vpart[1][b][1] + g_vpart[1][b][2] + g_vpart[1][b][3];
    float ip = 1.f / fmaxf(sp, EPSF);
    float ig = 1.f / fmaxf(sg, EPSF);
    const float* ps = g_cvv[0][b] + chunk * 4096;
    const float* gs = g_cvv[1][b] + chunk * 4096;
    float acc = 0.f;
    for (int i = tid; i < 4096; i += 1024) {
        float pn = ps[i] * ip, gn = gs[i] * ig;
        float kl = gn * logf((gn + EPSF) / (pn + EPSF));
        float d = pn - gn;
        acc += kl + d * d;
    }
    float tot = block_reduce(acc, red);
    if (tid == 0) g_dmpart[b][chunk] = tot;
}

// ---------------- kernel 5: Sinkhorn, register-resident fields + rowsum exchange ----------
// Separable stencil: t[y][x] = rs[y][x] + w1*(rs[y-1][x] + rs[y+1][x]),
// rs[y][x] = f[y][x] + w1*(f[y][x-1] + f[y][x+1]).  (w1^2 = w2 exactly.)
// Warp w owns rows {2w, 2w+1}; lane owns x = {2l, 2l+1}. u,v live in registers.
// Only row-sums hit smem (float2, double-buffered): 2 STS.64 + 2 LDS.64 per half-iter.
__global__ void __launch_bounds__(1024) k_sinkhorn()
{
    __shared__ float RSa[66 * 64], RSb[66 * 64];  // buffer row k = field row k-1; halos 0
    __shared__ float Uw[66 * 66];                 // padded final-u field for cost epilogue
    __shared__ float red[32];
    __shared__ float s4[4];
    int b = blockIdx.x;
    int tid = threadIdx.x;
    int w = tid >> 5, lane = tid & 31;
    unsigned M = 0xffffffffu;

    for (int i = tid; i < 66 * 64; i += 1024) { RSa[i] = 0.f; RSb[i] = 0.f; }
    for (int i = tid; i < 66 * 66; i += 1024) Uw[i] = 0.f;

    if (w < 4) {  // reduce the 64 per-block partials for each array
        int arr = w >> 1;
        float v = g_spart[arr][b][((w & 1) << 5) + lane];
#pragma unroll
        for (int o = 16; o > 0; o >>= 1) v += __shfl_down_sync(M, v, o);
        if (lane == 0) s4[w] = v;
    }
    __syncthreads();
    float asum = fmaxf(s4[0] + s4[1], EPSF);
    float bsum = fmaxf(s4[2] + s4[3], EPSF);

    const float w1 = expf(-10.f);
    const float w2 = expf(-20.f);
    int y0 = 2 * w, y1 = y0 + 1, x0 = 2 * lane;
    const float* pa = g_ot8[0][b];
    const float* pb = g_ot8[1][b];
    float a00 = pa[y0 * 64 + x0] / asum, a01 = pa[y0 * 64 + x0 + 1] / asum;
    float a10 = pa[y1 * 64 + x0] / asum, a11 = pa[y1 * 64 + x0 + 1] / asum;
    float b00 = pb[y0 * 64 + x0] / bsum, b01 = pb[y0 * 64 + x0 + 1] / bsum;
    float b10 = pb[y1 * 64 + x0] / bsum, b11 = pb[y1 * 64 + x0 + 1] / bsum;

    float2* A2 = reinterpret_cast<float2*>(RSa);
    float2* B2 = reinterpret_cast<float2*>(RSb);
    float u00 = 1.f, u01 = 1.f, u10 = 1.f, u11 = 1.f;
    float v00, v01, v10, v11;

    for (int it = 0; it < 50; ++it) {
        // ---- half A: v = b / (K @ u), buffer A ----
        {
            float fl0 = __shfl_up_sync(M, u01, 1);   if (lane == 0)  fl0 = 0.f;
            float fr0 = __shfl_down_sync(M, u00, 1); if (lane == 31) fr0 = 0.f;
            float fl1 = __shfl_up_sync(M, u11, 1);   if (lane == 0)  fl1 = 0.f;
            float fr1 = __shfl_down_sync(M, u10, 1); if (lane == 31) fr1 = 0.f;
            float2 rs0 = make_float2(fmaf(w1, fl0 + u01, u00), fmaf(w1, u00 + fr0, u01));
            float2 rs1 = make_float2(fmaf(w1, fl1 + u11, u10), fmaf(w1, u10 + fr1, u11));
            A2[(y0 + 1) * 32 + lane] = rs0;
            A2[(y1 + 1) * 32 + lane] = rs1;
            __syncthreads();
            float2 top = A2[y0 * 32 + lane];         // field row y0-1
            float2 bot = A2[(y1 + 2) * 32 + lane];   // field row y1+1
            float t00 = fmaf(w1, top.x + rs1.x, rs0.x);
            float t01 = fmaf(w1, top.y + rs1.y, rs0.y);
            float t10 = fmaf(w1, rs0.x + bot.x, rs1.x);
            float t11 = fmaf(w1, rs0.y + bot.y, rs1.y);
            v00 = __fdividef(b00, t00 + EPSF);
            v01 = __fdividef(b01, t01 + EPSF);
            v10 = __fdividef(b10, t10 + EPSF);
            v11 = __fdividef(b11, t11 + EPSF);
        }
        // ---- half B: u = a / (K @ v), buffer B ----
        {
            float fl0 = __shfl_up_sync(M, v01, 1);   if (lane == 0)  fl0 = 0.f;
            float fr0 = __shfl_down_sync(M, v00, 1); if (lane == 31) fr0 = 0.f;
            float fl1 = __shfl_up_sync(M, v11, 1);   if (lane == 0)  fl1 = 0.f;
            float fr1 = __shfl_down_sync(M, v10, 1); if (lane == 31) fr1 = 0.f;
            float2 rs0 = make_float2(fmaf(w1, fl0 + v01, v00), fmaf(w1, v00 + fr0, v01));
            float2 rs1 = make_float2(fmaf(w1, fl1 + v11, v10), fmaf(w1, v10 + fr1, v11));
            B2[(y0 + 1) * 32 + lane] = rs0;
            B2[(y1 + 1) * 32 + lane] = rs1;
            __syncthreads();
            float2 top = B2[y0 * 32 + lane];
            float2 bot = B2[(y1 + 2) * 32 + lane];
            float t00 = fmaf(w1, top.x + rs1.x, rs0.x);
            float t01 = fmaf(w1, top.y + rs1.y, rs0.y);
            float t10 = fmaf(w1, rs0.x + bot.x, rs1.x);
            float t11 = fmaf(w1, rs0.y + bot.y, rs1.y);
            u00 = __fdividef(a00, t00 + EPSF);
            u01 = __fdividef(a01, t01 + EPSF);
            u10 = __fdividef(a10, t10 + EPSF);
            u11 = __fdividef(a11, t11 + EPSF);
        }
    }

    // ---- cost epilogue: sum_j v_j * (w1*S1(u) + 2*w2*S2(u)); diagonal C=0 ----
    {
        float* Ur = Uw + (y0 + 1) * 66 + (x0 + 1);
        Ur[0] = u00; Ur[1] = u01; Ur[66] = u10; Ur[67] = u11;
    }
    __syncthreads();
    float tw2 = 2.f * w2;
    float c = 0.f;
    {
        const float* p = Uw + (y0 + 1) * 66 + (x0 + 1);
        float s1 = p[-66] + p[66] + p[-1] + p[1];
        float s2 = p[-67] + p[-65] + p[65] + p[67];
        c += v00 * fmaf(w1, s1, tw2 * s2);
    }
    {
        const float* p = Uw + (y0 + 1) * 66 + (x0 + 2);
        float s1 = p[-66] + p[66] + p[-1] + p[1];
        float s2 = p[-67] + p[-65] + p[65] + p[67];
        c += v01 * fmaf(w1, s1, tw2 * s2);
    }
    {
        const float* p = Uw + (y1 + 1) * 66 + (x0 + 1);
        float s1 = p[-66] + p[66] + p[-1] + p[1];
        float s2 = p[-67] + p[-65] + p[65] + p[67];
        c += v10 * fmaf(w1, s1, tw2 * s2);
    }
    {
        const float* p = Uw + (y1 + 1) * 66 + (x0 + 2);
        float s1 = p[-66] + p[66] + p[-1] + p[1];
        float s2 = p[-67] + p[-65] + p[65] + p[67];
        c += v11 * fmaf(w1, s1, tw2 * s2);
    }
    float tot = block_reduce(c, red);
    if (tid == 0) {
        g_sums[0][b] = asum;
        g_sums[1][b] = bsum;
        bool mask = (asum > 0.5f) && (bsum > 0.5f);
        g_ot_pb[b] = mask ? tot : 0.f;
    }
}

// ---------------- kernel 6: final scalar (single writer -> deterministic) ----------------
__global__ void __launch_bounds__(32) k_final(const int* __restrict__ gt_counts,
                                              const int* __restrict__ cell_area,
                                              float* __restrict__ out)
{
    int lane = threadIdx.x;
    float cl = 0.f, dm = 0.f, ot = 0.f;
    if (lane < BATCH) {
        int craw = cell_area[0];
        // robust to int32 or float32 encoding of the scalar (both yield 1.0 here)
        float ca = (craw >= 1 && craw <= 1000000) ? (float)craw : __int_as_float(craw);
        float pc = fmaxf(g_sums[0][lane] / ca, 0.f);
        float d = fabsf(pc - (float)gt_counts[lane]);
        cl = (d < 10.f) ? (0.5f * d * d / 10.f) : (d - 5.f);
        dm = g_dmpart[lane][0] + g_dmpart[lane][1] + g_dmpart[lane][2] + g_dmpart[lane][3];
        ot = g_ot_pb[lane];
    }
#pragma unroll
    for (int o = 16; o > 0; o >>= 1) {
        cl += __shfl_down_sync(0xffffffffu, cl, o);
        dm += __shfl_down_sync(0xffffffffu, dm, o);
        ot += __shfl_down_sync(0xffffffffu, ot, o);
    }
    if (lane == 0)
        out[0] = 3.0f * (cl * (1.f / 16.f)) + 0.5f * (dm * (1.f / 16.f)) + 0.3f * (ot * (1.f / 16.f));
}

// ---------------- launch ----------------
extern "C" void kernel_launch(void* const* d_in, const int* in_sizes, int n_in,
                              void* d_out, int out_size)
{
    const float* pred = (const float*)d_in[0];
    const float* gt = (const float*)d_in[1];
    const int* counts = (const int*)d_in[2];
    const int* cell = (const int*)d_in[3];
    float* out = (float*)d_out;

    k_blocksum4<<<dim3(4, 16, 32), dim3(32, 8)>>>(pred, gt);
    k_convh<<<dim3(4, 32), 256>>>();
    k_convv<<<dim3(4, 32), 256>>>();
    k_dmloss<<<dim3(4, 16), 1024>>>();
    k_sinkhorn<<<16, 1024>>>();
    k_final<<<1, 32>>>(counts, cell, out);
}

// round 10
// speedup vs baseline: 2.0095x; 1.0423x over previous
#include <cuda_runtime.h>
#include <math.h>

#define EPSF 1e-8f
#define BATCH 16

// ---------------- scratch (device globals; no allocation allowed) ----------------
__device__ float g_dm4[2][BATCH][128 * 128];   // block-4 sums (p=0, g=1)
__device__ float g_cvh[2][BATCH][128 * 128];   // horizontal gaussian pass
__device__ float g_cvv[2][BATCH][128 * 128];   // vertical gaussian pass (smoothed)
__device__ float g_ot8[2][BATCH][64 * 64];     // block-8 sums
__device__ float g_spart[2][BATCH][64];        // per-block partial sums of density
__device__ float g_sums[2][BATCH];             // per-batch totals (written by sinkhorn)
__device__ float g_vpart[2][BATCH][4];         // per-chunk sums of smoothed field
__device__ float g_dmpart[BATCH][16];          // per-chunk kl+l2 partials
__device__ float g_ot_pb[BATCH];               // per-batch masked OT cost

// ---------------- helpers ----------------
__device__ __forceinline__ float block_reduce(float v, float* scratch)
{
    int tid = threadIdx.x + threadIdx.y * blockDim.x;
    unsigned m = 0xffffffffu;
#pragma unroll
    for (int o = 16; o > 0; o >>= 1) v += __shfl_down_sync(m, v, o);
    int lane = tid & 31, w = tid >> 5;
    int nw = (blockDim.x * blockDim.y + 31) >> 5;
    if (lane == 0) scratch[w] = v;
    __syncthreads();
    v = (tid < nw) ? scratch[tid] : 0.f;
    __syncthreads();
    if (w == 0) {
#pragma unroll
        for (int o = 16; o > 0; o >>= 1) v += __shfl_down_sync(m, v, o);
    }
    return v;  // valid in thread 0
}

__device__ __forceinline__ void make_gauss(float* gk, float* ginv, int tid)
{
    if (tid < 49) {
        float d = (float)tid - 24.f;
        gk[tid] = expf(-(d * d) * (1.f / 128.f));
    }
    __syncthreads();
    if (tid == 0) {
        float s = 0.f;
        for (int i = 0; i < 49; ++i) s += gk[i];
        *ginv = 1.f / s;
    }
    __syncthreads();
}

// ---- kernel 1: 4x4 block sums + fused 8x8 ot cells + per-block partial sums ----
__global__ void __launch_bounds__(256) k_blocksum4(const float* __restrict__ pred,
                                                   const float* __restrict__ gt)
{
    __shared__ float sm[8][33];
    __shared__ float red[32];
    int z = blockIdx.z;
    int arr = z >> 4, b = z & 15;
    const float* in = (arr ? gt : pred) + (size_t)b * 512 * 512;
    int tx = threadIdx.x, ty = threadIdx.y;
    int x = blockIdx.x * 32 + tx;   // dm4 col 0..127
    int y = blockIdx.y * 8 + ty;    // dm4 row 0..127
    float s = 0.f;
#pragma unroll
    for (int r = 0; r < 4; ++r) {
        float4 v = *reinterpret_cast<const float4*>(in + (size_t)(4 * y + r) * 512 + 4 * x);
        s += v.x + v.y + v.z + v.w;
    }
    g_dm4[arr][b][y * 128 + x] = s;
    sm[ty][tx] = s;
    float tot = block_reduce(s, red);   // contains syncs -> sm visible after
    int tid = ty * 32 + tx;
    if (tid == 0) g_spart[arr][b][blockIdx.y * 4 + blockIdx.x] = tot;
    if (tid < 64) {
        int r = tid >> 4, cc = tid & 15;
        float v = sm[2 * r][2 * cc] + sm[2 * r][2 * cc + 1] +
                  sm[2 * r + 1][2 * cc] + sm[2 * r + 1][2 * cc + 1];
        g_ot8[arr][b][(blockIdx.y * 4 + r) * 64 + blockIdx.x * 16 + cc] = v;
    }
}

// ---- kernel 2: horizontal 49-tap gaussian, 16 outputs/thread, register window ----
__global__ void __launch_bounds__(256) k_convh()
{
    __shared__ float s[32][177];   // cols [24,152) hold data, rest zero pad
    __shared__ float gk[49];
    __shared__ float ginv;
    int img = blockIdx.y;
    int arr = img >> 4, bb = img & 15;
    int rowbase = blockIdx.x * 32;
    int tid = threadIdx.x;  // 256
    const float* in = g_dm4[arr][bb];
    float* out = g_cvh[arr][bb];
    make_gauss(gk, &ginv, tid);
    for (int i = tid; i < 32 * 177; i += 256) (&s[0][0])[i] = 0.f;
    __syncthreads();
    for (int i = tid; i < 32 * 128; i += 256) {
        int r = i >> 7, c = i & 127;
        s[r][c + 24] = in[(rowbase + r) * 128 + c];
    }
    __syncthreads();
    int lane = tid & 31;          // row within chunk
    int x0 = (tid >> 5) * 16;     // warp -> 16-wide x group
    const float* srow = &s[lane][x0];
    float win[64];
#pragma unroll
    for (int t = 0; t < 64; ++t) win[t] = srow[t];
    float acc[16];
#pragma unroll
    for (int k = 0; k < 16; ++k) acc[k] = 0.f;
#pragma unroll
    for (int j = 0; j < 49; ++j) {
        float wj = gk[j];
#pragma unroll
        for (int k = 0; k < 16; ++k) acc[k] = fmaf(wj, win[j + k], acc[k]);
    }
    float gi = ginv;
    float* op = out + (rowbase + lane) * 128 + x0;
#pragma unroll
    for (int k = 0; k < 16; k += 4) {
        float4 v = make_float4(acc[k] * gi, acc[k + 1] * gi, acc[k + 2] * gi, acc[k + 3] * gi);
        *reinterpret_cast<float4*>(op + k) = v;
    }
}

// ---- kernel 3: vertical 49-tap gaussian, 16 outputs/thread, register window ----
__global__ void __launch_bounds__(256) k_convv()
{
    __shared__ float s[80 * 128];
    __shared__ float gk[49];
    __shared__ float ginv;
    __shared__ float red[32];
    int img = blockIdx.y;
    int arr = img >> 4, bb = img & 15;
    int ybase = blockIdx.x * 32;
    int tid = threadIdx.x;  // 256
    const float* in = g_cvh[arr][bb];
    float* out = g_cvv[arr][bb];
    make_gauss(gk, &ginv, tid);
    for (int i = tid; i < 80 * 128; i += 256) {
        int r = i >> 7, x = i & 127;
        int sy = ybase - 24 + r;
        s[i] = (sy >= 0 && sy < 128) ? in[sy * 128 + x] : 0.f;
    }
    __syncthreads();
    int x = tid & 127;
    int yo = (tid >> 7) * 16;  // 0 or 16: local output base
    const float* col0 = &s[yo * 128 + x];
    float win[64];
#pragma unroll
    for (int t = 0; t < 64; ++t) win[t] = col0[t * 128];
    float acc[16];
#pragma unroll
    for (int k = 0; k < 16; ++k) acc[k] = 0.f;
#pragma unroll
    for (int j = 0; j < 49; ++j) {
        float wj = gk[j];
#pragma unroll
        for (int k = 0; k < 16; ++k) acc[k] = fmaf(wj, win[j + k], acc[k]);
    }
    float gi = ginv;
    float loc = 0.f;
#pragma unroll
    for (int k = 0; k < 16; ++k) {
        float v = acc[k] * gi;
        out[(ybase + yo + k) * 128 + x] = v;
        loc += v;
    }
    float tot = block_reduce(loc, red);
    if (tid == 0) g_vpart[arr][bb][blockIdx.x] = tot;
}

// ---- kernel 4: DM KL + L2 (256 blocks x 256 threads, float4, fast log) ----
__global__ void __launch_bounds__(256) k_dmloss()
{
    __shared__ float red[32];
    int chunk = blockIdx.x, b = blockIdx.y;
    int tid = threadIdx.x;
    float sp = g_vpart[0][b][0] + g_vpart[0][b][1] + g_vpart[0][b][2] + g_vpart[0][b][3];
    float sg = g_vpart[1][b][0] + g_vpart[1][b][1] + g_vpart[1][b][2] + g_vpart[1][b][3];
    float ip = 1.f / fmaxf(sp, EPSF);
    float ig = 1.f / fmaxf(sg, EPSF);
    const float4* ps = reinterpret_cast<const float4*>(g_cvv[0][b] + chunk * 1024);
    const float4* gs = reinterpret_cast<const float4*>(g_cvv[1][b] + chunk * 1024);
    float4 pv = ps[tid];
    float4 gv = gs[tid];
    float acc = 0.f;
#pragma unroll
    for (int k = 0; k < 4; ++k) {
        float pn = (&pv.x)[k] * ip, gn = (&gv.x)[k] * ig;
        float kl = gn * __logf(__fdividef(gn + EPSF, pn + EPSF));
        float d = pn - gn;
        acc += kl + d * d;
    }
    float tot = block_reduce(acc, red);
    if (tid == 0) g_dmpart[b][chunk] = tot;
}

// ---------------- kernel 5: Sinkhorn, register-resident fields + rowsum exchange ----------
// Separable stencil: t[y][x] = rs[y][x] + w1*(rs[y-1][x] + rs[y+1][x]),
// rs[y][x] = f[y][x] + w1*(f[y][x-1] + f[y][x+1]).  (w1^2 = w2 exactly.)
__global__ void __launch_bounds__(1024) k_sinkhorn()
{
    __shared__ float RSa[66 * 64], RSb[66 * 64];  // buffer row k = field row k-1; halos 0
    __shared__ float Uw[66 * 66];                 // padded final-u field for cost epilogue
    __shared__ float red[32];
    __shared__ float s4[4];
    int b = blockIdx.x;
    int tid = threadIdx.x;
    int w = tid >> 5, lane = tid & 31;
    unsigned M = 0xffffffffu;

    for (int i = tid; i < 66 * 64; i += 1024) { RSa[i] = 0.f; RSb[i] = 0.f; }
    for (int i = tid; i < 66 * 66; i += 1024) Uw[i] = 0.f;

    if (w < 4) {  // reduce the 64 per-block partials for each array
        int arr = w >> 1;
        float v = g_spart[arr][b][((w & 1) << 5) + lane];
#pragma unroll
        for (int o = 16; o > 0; o >>= 1) v += __shfl_down_sync(M, v, o);
        if (lane == 0) s4[w] = v;
    }
    __syncthreads();
    float asum = fmaxf(s4[0] + s4[1], EPSF);
    float bsum = fmaxf(s4[2] + s4[3], EPSF);

    const float w1 = expf(-10.f);
    const float w2 = expf(-20.f);
    int y0 = 2 * w, y1 = y0 + 1, x0 = 2 * lane;
    const float* pa = g_ot8[0][b];
    const float* pb = g_ot8[1][b];
    float a00 = pa[y0 * 64 + x0] / asum, a01 = pa[y0 * 64 + x0 + 1] / asum;
    float a10 = pa[y1 * 64 + x0] / asum, a11 = pa[y1 * 64 + x0 + 1] / asum;
    float b00 = pb[y0 * 64 + x0] / bsum, b01 = pb[y0 * 64 + x0 + 1] / bsum;
    float b10 = pb[y1 * 64 + x0] / bsum, b11 = pb[y1 * 64 + x0 + 1] / bsum;

    float2* A2 = reinterpret_cast<float2*>(RSa);
    float2* B2 = reinterpret_cast<float2*>(RSb);
    float u00 = 1.f, u01 = 1.f, u10 = 1.f, u11 = 1.f;
    float v00, v01, v10, v11;

    for (int it = 0; it < 50; ++it) {
        // ---- half A: v = b / (K @ u), buffer A ----
        {
            float fl0 = __shfl_up_sync(M, u01, 1);   if (lane == 0)  fl0 = 0.f;
            float fr0 = __shfl_down_sync(M, u00, 1); if (lane == 31) fr0 = 0.f;
            float fl1 = __shfl_up_sync(M, u11, 1);   if (lane == 0)  fl1 = 0.f;
            float fr1 = __shfl_down_sync(M, u10, 1); if (lane == 31) fr1 = 0.f;
            float2 rs0 = make_float2(fmaf(w1, fl0 + u01, u00), fmaf(w1, u00 + fr0, u01));
            float2 rs1 = make_float2(fmaf(w1, fl1 + u11, u10), fmaf(w1, u10 + fr1, u11));
            A2[(y0 + 1) * 32 + lane] = rs0;
            A2[(y1 + 1) * 32 + lane] = rs1;
            __syncthreads();
            float2 top = A2[y0 * 32 + lane];         // field row y0-1
            float2 bot = A2[(y1 + 2) * 32 + lane];   // field row y1+1
            float t00 = fmaf(w1, top.x + rs1.x, rs0.x);
            float t01 = fmaf(w1, top.y + rs1.y, rs0.y);
            float t10 = fmaf(w1, rs0.x + bot.x, rs1.x);
            float t11 = fmaf(w1, rs0.y + bot.y, rs1.y);
            v00 = __fdividef(b00, t00 + EPSF);
            v01 = __fdividef(b01, t01 + EPSF);
            v10 = __fdividef(b10, t10 + EPSF);
            v11 = __fdividef(b11, t11 + EPSF);
        }
        // ---- half B: u = a / (K @ v), buffer B ----
        {
            float fl0 = __shfl_up_sync(M, v01, 1);   if (lane == 0)  fl0 = 0.f;
            float fr0 = __shfl_down_sync(M, v00, 1); if (lane == 31) fr0 = 0.f;
            float fl1 = __shfl_up_sync(M, v11, 1);   if (lane == 0)  fl1 = 0.f;
            float fr1 = __shfl_down_sync(M, v10, 1); if (lane == 31) fr1 = 0.f;
            float2 rs0 = make_float2(fmaf(w1, fl0 + v01, v00), fmaf(w1, v00 + fr0, v01));
            float2 rs1 = make_float2(fmaf(w1, fl1 + v11, v10), fmaf(w1, v10 + fr1, v11));
            B2[(y0 + 1) * 32 + lane] = rs0;
            B2[(y1 + 1) * 32 + lane] = rs1;
            __syncthreads();
            float2 top = B2[y0 * 32 + lane];
            float2 bot = B2[(y1 + 2) * 32 + lane];
            float t00 = fmaf(w1, top.x + rs1.x, rs0.x);
            float t01 = fmaf(w1, top.y + rs1.y, rs0.y);
            float t10 = fmaf(w1, rs0.x + bot.x, rs1.x);
            float t11 = fmaf(w1, rs0.y + bot.y, rs1.y);
            u00 = __fdividef(a00, t00 + EPSF);
            u01 = __fdividef(a01, t01 + EPSF);
            u10 = __fdividef(a10, t10 + EPSF);
            u11 = __fdividef(a11, t11 + EPSF);
        }
    }

    // ---- cost epilogue: sum_j v_j * (w1*S1(u) + 2*w2*S2(u)); diagonal C=0 ----
    {
        float* Ur = Uw + (y0 + 1) * 66 + (x0 + 1);
        Ur[0] = u00; Ur[1] = u01; Ur[66] = u10; Ur[67] = u11;
    }
    __syncthreads();
    float tw2 = 2.f * w2;
    float c = 0.f;
    {
        const float* p = Uw + (y0 + 1) * 66 + (x0 + 1);
        float s1 = p[-66] + p[66] + p[-1] + p[1];
        float s2 = p[-67] + p[-65] + p[65] + p[67];
        c += v00 * fmaf(w1, s1, tw2 * s2);
    }
    {
        const float* p = Uw + (y0 + 1) * 66 + (x0 + 2);
        float s1 = p[-66] + p[66] + p[-1] + p[1];
        float s2 = p[-67] + p[-65] + p[65] + p[67];
        c += v01 * fmaf(w1, s1, tw2 * s2);
    }
    {
        const float* p = Uw + (y1 + 1) * 66 + (x0 + 1);
        float s1 = p[-66] + p[66] + p[-1] + p[1];
        float s2 = p[-67] + p[-65] + p[65] + p[67];
        c += v10 * fmaf(w1, s1, tw2 * s2);
    }
    {
        const float* p = Uw + (y1 + 1) * 66 + (x0 + 2);
        float s1 = p[-66] + p[66] + p[-1] + p[1];
        float s2 = p[-67] + p[-65] + p[65] + p[67];
        c += v11 * fmaf(w1, s1, tw2 * s2);
    }
    float tot = block_reduce(c, red);
    if (tid == 0) {
        g_sums[0][b] = asum;
        g_sums[1][b] = bsum;
        bool mask = (asum > 0.5f) && (bsum > 0.5f);
        g_ot_pb[b] = mask ? tot : 0.f;
    }
}

// ---------------- kernel 6: final scalar (single writer -> deterministic) ----------------
__global__ void __launch_bounds__(32) k_final(const int* __restrict__ gt_counts,
                                              const int* __restrict__ cell_area,
                                              float* __restrict__ out)
{
    int lane = threadIdx.x;
    float cl = 0.f, dm = 0.f, ot = 0.f;
    if (lane < BATCH) {
        int craw = cell_area[0];
        // robust to int32 or float32 encoding of the scalar (both yield 1.0 here)
        float ca = (craw >= 1 && craw <= 1000000) ? (float)craw : __int_as_float(craw);
        float pc = fmaxf(g_sums[0][lane] / ca, 0.f);
        float d = fabsf(pc - (float)gt_counts[lane]);
        cl = (d < 10.f) ? (0.5f * d * d / 10.f) : (d - 5.f);
#pragma unroll
        for (int c = 0; c < 16; ++c) dm += g_dmpart[lane][c];
        ot = g_ot_pb[lane];
    }
#pragma unroll
    for (int o = 16; o > 0; o >>= 1) {
        cl += __shfl_down_sync(0xffffffffu, cl, o);
        dm += __shfl_down_sync(0xffffffffu, dm, o);
        ot += __shfl_down_sync(0xffffffffu, ot, o);
    }
    if (lane == 0)
        out[0] = 3.0f * (cl * (1.f / 16.f)) + 0.5f * (dm * (1.f / 16.f)) + 0.3f * (ot * (1.f / 16.f));
}

// ---------------- launch ----------------
extern "C" void kernel_launch(void* const* d_in, const int* in_sizes, int n_in,
                              void* d_out, int out_size)
{
    const float* pred = (const float*)d_in[0];
    const float* gt = (const float*)d_in[1];
    const int* counts = (const int*)d_in[2];
    const int* cell = (const int*)d_in[3];
    float* out = (float*)d_out;

    k_blocksum4<<<dim3(4, 16, 32), dim3(32, 8)>>>(pred, gt);
    k_convh<<<dim3(4, 32), 256>>>();
    k_convv<<<dim3(4, 32), 256>>>();
    k_dmloss<<<dim3(16, 16), 256>>>();
    k_sinkhorn<<<16, 1024>>>();
    k_final<<<1, 32>>>(counts, cell, out);
}

// round 13
// speedup vs baseline: 2.1470x; 1.0685x over previous
#include <cuda_runtime.h>
#include <math.h>

#define EPSF 1e-8f
#define BATCH 16
#define NBLK3 144   // 16 sinkhorn + 128 dmloss blocks in k_back

// ---------------- scratch (device globals; no allocation allowed) ----------------
__device__ float g_cvh[2][BATCH][128 * 128];   // horizontal gaussian pass
__device__ float g_cvv[2][BATCH][128 * 128];   // vertical gaussian pass (smoothed)
__device__ float g_ot8[2][BATCH][64 * 64];     // block-8 sums
__device__ float g_spart[2][BATCH][16];        // per-rowchunk partial sums of density
__device__ float g_sums[2][BATCH];             // per-batch totals (written by sinkhorn)
__device__ float g_vpart[2][BATCH][4];         // per-chunk sums of smoothed field
__device__ float g_dmpart[BATCH][8];           // per-chunk kl+l2 partials
__device__ float g_ot_pb[BATCH];               // per-batch masked OT cost
__device__ unsigned g_ctr = 0;                 // arrival counter for k_back (self-resetting)

// ---------------- helpers ----------------
__device__ __forceinline__ float block_reduce(float v, float* scratch)
{
    int tid = threadIdx.x + threadIdx.y * blockDim.x;
    unsigned m = 0xffffffffu;
#pragma unroll
    for (int o = 16; o > 0; o >>= 1) v += __shfl_down_sync(m, v, o);
    int lane = tid & 31, w = tid >> 5;
    int nw = (blockDim.x * blockDim.y + 31) >> 5;
    if (lane == 0) scratch[w] = v;
    __syncthreads();
    v = (tid < nw) ? scratch[tid] : 0.f;
    __syncthreads();
    if (w == 0) {
#pragma unroll
        for (int o = 16; o > 0; o >>= 1) v += __shfl_down_sync(m, v, o);
    }
    return v;  // valid in thread 0
}

__device__ __forceinline__ void make_gauss(float* gk, float* ginv, int tid)
{
    if (tid < 49) {
        float d = (float)tid - 24.f;
        gk[tid] = expf(-(d * d) * (1.f / 128.f));
    }
    __syncthreads();
    if (tid == 0) {
        float s = 0.f;
        for (int i = 0; i < 49; ++i) s += gk[i];
        *ginv = 1.f / s;
    }
    __syncthreads();
}

// ==== K1: 4x4 block sums + fused horizontal gaussian + ot8 cells + partial sums ====
// Block = dm4 rows [8*ych, 8*ych+8) x all 128 cols  (x-halo is in-block => no g_dm4 array).
__global__ void __launch_bounds__(256) k_front(const float* __restrict__ pred,
                                               const float* __restrict__ gt)
{
    __shared__ float sdm[8][176];   // cols [24,152) = dm4 data, rest zero
    __shared__ float gk[49];
    __shared__ float ginv;
    __shared__ float red[32];
    int ych = blockIdx.x;           // 0..15
    int img = blockIdx.y;
    int arr = img >> 4, b = img & 15;
    const float* in = (arr ? gt : pred) + (size_t)b * 512 * 512;
    int tid = threadIdx.x;

    for (int i = tid; i < 8 * 176; i += 256) (&sdm[0][0])[i] = 0.f;
    make_gauss(gk, &ginv, tid);     // syncs inside also publish the zeroed smem

    // 4x4 block sums into smem (+ per-thread partial for spart)
    float psum = 0.f;
    for (int i = tid; i < 1024; i += 256) {
        int r = i >> 7, c = i & 127;
        float s = 0.f;
#pragma unroll
        for (int rr = 0; rr < 4; ++rr) {
            float4 v = *reinterpret_cast<const float4*>(
                in + (size_t)(ych * 32 + 4 * r + rr) * 512 + 4 * c);
            s += v.x + v.y + v.z + v.w;
        }
        sdm[r][c + 24] = s;
        psum += s;
    }
    __syncthreads();

    // 8x8 ot cells (2x2 of dm4) for this 8-row band
    {
        int rr = tid >> 6, cc = tid & 63;   // 4 rows x 64 cols = 256 cells
        float v = sdm[2 * rr][2 * cc + 24] + sdm[2 * rr][2 * cc + 25] +
                  sdm[2 * rr + 1][2 * cc + 24] + sdm[2 * rr + 1][2 * cc + 25];
        g_ot8[arr][b][(ych * 4 + rr) * 64 + cc] = v;
    }

    // per-band density partial sum (block_reduce contains syncs; sdm untouched after)
    float tot = block_reduce(psum, red);
    if (tid == 0) g_spart[arr][b][ych] = tot;

    // horizontal 49-tap conv: thread = (row, lane), 4 outputs strided by 32 (stride-1 LDS)
    int r = tid >> 5, tx = tid & 31;
    float acc[4] = {0.f, 0.f, 0.f, 0.f};
#pragma unroll
    for (int j = 0; j < 49; ++j) {
        float wj = gk[j];
#pragma unroll
        for (int k = 0; k < 4; ++k) acc[k] = fmaf(wj, sdm[r][tx + 32 * k + j], acc[k]);
    }
    float gi = ginv;
    float* op = g_cvh[arr][b] + (ych * 8 + r) * 128 + tx;
#pragma unroll
    for (int k = 0; k < 4; ++k) op[32 * k] = acc[k] * gi;
}

// ==== K2: vertical 49-tap gaussian, 16 outputs/thread, register window + partial sums ====
__global__ void __launch_bounds__(256) k_convv()
{
    __shared__ float s[80 * 128];
    __shared__ float gk[49];
    __shared__ float ginv;
    __shared__ float red[32];
    int img = blockIdx.y;
    int arr = img >> 4, bb = img & 15;
    int ybase = blockIdx.x * 32;
    int tid = threadIdx.x;  // 256
    const float* in = g_cvh[arr][bb];
    float* out = g_cvv[arr][bb];
    make_gauss(gk, &ginv, tid);
    for (int i = tid; i < 80 * 128; i += 256) {
        int r = i >> 7, x = i & 127;
        int sy = ybase - 24 + r;
        s[i] = (sy >= 0 && sy < 128) ? in[sy * 128 + x] : 0.f;
    }
    __syncthreads();
    int x = tid & 127;
    int yo = (tid >> 7) * 16;  // 0 or 16: local output base
    const float* col0 = &s[yo * 128 + x];
    float win[64];
#pragma unroll
    for (int t = 0; t < 64; ++t) win[t] = col0[t * 128];
    float acc[16];
#pragma unroll
    for (int k = 0; k < 16; ++k) acc[k] = 0.f;
#pragma unroll
    for (int j = 0; j < 49; ++j) {
        float wj = gk[j];
#pragma unroll
        for (int k = 0; k < 16; ++k) acc[k] = fmaf(wj, win[j + k], acc[k]);
    }
    float gi = ginv;
    float loc = 0.f;
#pragma unroll
    for (int k = 0; k < 16; ++k) {
        float v = acc[k] * gi;
        out[(ybase + yo + k) * 128 + x] = v;
        loc += v;
    }
    float tot = block_reduce(loc, red);
    if (tid == 0) g_vpart[arr][bb][blockIdx.x] = tot;
}

// ==== K3: sinkhorn (blocks 0-15) + dm KL/L2 (blocks 16-143) + final via last-block ====
// Sinkhorn: separable stencil t = rs + w1*(rs_up + rs_down), rs = f + w1*(f_l + f_r),
// with w1^2 = w2 exactly. u,v register-resident; only row-sums hit smem.
__global__ void __launch_bounds__(1024) k_back(const int* __restrict__ gt_counts,
                                               const int* __restrict__ cell_area,
                                               float* __restrict__ out)
{
    __shared__ float RSa[66 * 64], RSb[66 * 64];  // buffer row k = field row k-1; halos 0
    __shared__ float Uw[66 * 66];                 // padded final-u field for cost epilogue
    __shared__ float red[32];
    __shared__ float s2[2];
    __shared__ int lastf;
    int bid = blockIdx.x;
    int tid = threadIdx.x;
    int w = tid >> 5, lane = tid & 31;
    unsigned M = 0xffffffffu;
    if (tid == 0) lastf = 0;

    if (bid < 16) {
        // ---------------- Sinkhorn for batch b = bid ----------------
        int b = bid;
        for (int i = tid; i < 66 * 64; i += 1024) { RSa[i] = 0.f; RSb[i] = 0.f; }
        for (int i = tid; i < 66 * 66; i += 1024) Uw[i] = 0.f;
        if (w < 2) {  // reduce the 16 per-band partials per array
            float v = (lane < 16) ? g_spart[w][b][lane] : 0.f;
#pragma unroll
            for (int o = 16; o > 0; o >>= 1) v += __shfl_down_sync(M, v, o);
            if (lane == 0) s2[w] = v;
        }
        __syncthreads();
        float asum = fmaxf(s2[0], EPSF);
        float bsum = fmaxf(s2[1], EPSF);

        const float w1 = expf(-10.f);
        const float w2 = expf(-20.f);
        int y0 = 2 * w, y1 = y0 + 1, x0 = 2 * lane;
        const float* pa = g_ot8[0][b];
        const float* pb = g_ot8[1][b];
        float a00 = pa[y0 * 64 + x0] / asum, a01 = pa[y0 * 64 + x0 + 1] / asum;
        float a10 = pa[y1 * 64 + x0] / asum, a11 = pa[y1 * 64 + x0 + 1] / asum;
        float b00 = pb[y0 * 64 + x0] / bsum, b01 = pb[y0 * 64 + x0 + 1] / bsum;
        float b10 = pb[y1 * 64 + x0] / bsum, b11 = pb[y1 * 64 + x0 + 1] / bsum;

        float2* A2 = reinterpret_cast<float2*>(RSa);
        float2* B2 = reinterpret_cast<float2*>(RSb);
        float u00 = 1.f, u01 = 1.f, u10 = 1.f, u11 = 1.f;
        float v00, v01, v10, v11;

        for (int it = 0; it < 50; ++it) {
            {   // half A: v = b / (K @ u)
                float fl0 = __shfl_up_sync(M, u01, 1);   if (lane == 0)  fl0 = 0.f;
                float fr0 = __shfl_down_sync(M, u00, 1); if (lane == 31) fr0 = 0.f;
                float fl1 = __shfl_up_sync(M, u11, 1);   if (lane == 0)  fl1 = 0.f;
                float fr1 = __shfl_down_sync(M, u10, 1); if (lane == 31) fr1 = 0.f;
                float2 rs0 = make_float2(fmaf(w1, fl0 + u01, u00), fmaf(w1, u00 + fr0, u01));
                float2 rs1 = make_float2(fmaf(w1, fl1 + u11, u10), fmaf(w1, u10 + fr1, u11));
                A2[(y0 + 1) * 32 + lane] = rs0;
                A2[(y1 + 1) * 32 + lane] = rs1;
                __syncthreads();
                float2 top = A2[y0 * 32 + lane];
                float2 bot = A2[(y1 + 2) * 32 + lane];
                float t00 = fmaf(w1, top.x + rs1.x, rs0.x);
                float t01 = fmaf(w1, top.y + rs1.y, rs0.y);
                float t10 = fmaf(w1, rs0.x + bot.x, rs1.x);
                float t11 = fmaf(w1, rs0.y + bot.y, rs1.y);
                v00 = __fdividef(b00, t00 + EPSF);
                v01 = __fdividef(b01, t01 + EPSF);
                v10 = __fdividef(b10, t10 + EPSF);
                v11 = __fdividef(b11, t11 + EPSF);
            }
            {   // half B: u = a / (K @ v)
                float fl0 = __shfl_up_sync(M, v01, 1);   if (lane == 0)  fl0 = 0.f;
                float fr0 = __shfl_down_sync(M, v00, 1); if (lane == 31) fr0 = 0.f;
                float fl1 = __shfl_up_sync(M, v11, 1);   if (lane == 0)  fl1 = 0.f;
                float fr1 = __shfl_down_sync(M, v10, 1); if (lane == 31) fr1 = 0.f;
                float2 rs0 = make_float2(fmaf(w1, fl0 + v01, v00), fmaf(w1, v00 + fr0, v01));
                float2 rs1 = make_float2(fmaf(w1, fl1 + v11, v10), fmaf(w1, v10 + fr1, v11));
                B2[(y0 + 1) * 32 + lane] = rs0;
                B2[(y1 + 1) * 32 + lane] = rs1;
                __syncthreads();
                float2 top = B2[y0 * 32 + lane];
                float2 bot = B2[(y1 + 2) * 32 + lane];
                float t00 = fmaf(w1, top.x + rs1.x, rs0.x);
                float t01 = fmaf(w1, top.y + rs1.y, rs0.y);
                float t10 = fmaf(w1, rs0.x + bot.x, rs1.x);
                float t11 = fmaf(w1, rs0.y + bot.y, rs1.y);
                u00 = __fdividef(a00, t00 + EPSF);
                u01 = __fdividef(a01, t01 + EPSF);
                u10 = __fdividef(a10, t10 + EPSF);
                u11 = __fdividef(a11, t11 + EPSF);
            }
        }

        // cost epilogue: sum_j v_j * (w1*S1(u) + 2*w2*S2(u)); diagonal C=0
        {
            float* Ur = Uw + (y0 + 1) * 66 + (x0 + 1);
            Ur[0] = u00; Ur[1] = u01; Ur[66] = u10; Ur[67] = u11;
        }
        __syncthreads();
        float tw2 = 2.f * w2;
        float c = 0.f;
        {
            const float* p = Uw + (y0 + 1) * 66 + (x0 + 1);
            float s1v = p[-66] + p[66] + p[-1] + p[1];
            float s2v = p[-67] + p[-65] + p[65] + p[67];
            c += v00 * fmaf(w1, s1v, tw2 * s2v);
        }
        {
            const float* p = Uw + (y0 + 1) * 66 + (x0 + 2);
            float s1v = p[-66] + p[66] + p[-1] + p[1];
            float s2v = p[-67] + p[-65] + p[65] + p[67];
            c += v01 * fmaf(w1, s1v, tw2 * s2v);
        }
        {
            const float* p = Uw + (y1 + 1) * 66 + (x0 + 1);
            float s1v = p[-66] + p[66] + p[-1] + p[1];
            float s2v = p[-67] + p[-65] + p[65] + p[67];
            c += v10 * fmaf(w1, s1v, tw2 * s2v);
        }
        {
            const float* p = Uw + (y1 + 1) * 66 + (x0 + 2);
            float s1v = p[-66] + p[66] + p[-1] + p[1];
            float s2v = p[-67] + p[-65] + p[65] + p[67];
            c += v11 * fmaf(w1, s1v, tw2 * s2v);
        }
        float tot = block_reduce(c, red);
        if (tid == 0) {
            g_sums[0][b] = asum;
            g_sums[1][b] = bsum;
            bool mask = (asum > 0.5f) && (bsum > 0.5f);
            g_ot_pb[b] = mask ? tot : 0.f;
        }
    } else {
        // ---------------- DM KL + L2 chunk ----------------
        int idx = bid - 16;
        int b = idx >> 3, chunk = idx & 7;   // 8 chunks x 2048 elems
        float sp = g_vpart[0][b][0] + g_vpart[0][b][1] + g_vpart[0][b][2] + g_vpart[0][b][3];
        float sg = g_vpart[1][b][0] + g_vpart[1][b][1] + g_vpart[1][b][2] + g_vpart[1][b][3];
        float ip = 1.f / fmaxf(sp, EPSF);
        float ig = 1.f / fmaxf(sg, EPSF);
        const float2* ps = reinterpret_cast<const float2*>(g_cvv[0][b] + chunk * 2048);
        const float2* gs = reinterpret_cast<const float2*>(g_cvv[1][b] + chunk * 2048);
        float2 pv = ps[tid];
        float2 gv = gs[tid];
        float acc = 0.f;
#pragma unroll
        for (int k = 0; k < 2; ++k) {
            float pn = (&pv.x)[k] * ip, gn = (&gv.x)[k] * ig;
            float kl = gn * __logf(__fdividef(gn + EPSF, pn + EPSF));
            float d = pn - gn;
            acc += kl + d * d;
        }
        float tot = block_reduce(acc, red);
        if (tid == 0) g_dmpart[b][chunk] = tot;
    }

    // ---------------- last-block final (deterministic: fenced partials, single writer) ----
    if (tid == 0) {
        __threadfence();
        if (atomicAdd(&g_ctr, 1u) == (unsigned)(NBLK3 - 1)) lastf = 1;
    }
    __syncthreads();
    if (lastf && w == 0) {
        __threadfence();  // acquire: order reads after the counter observation
        if (lane == 0) g_ctr = 0;  // self-reset for next launch/replay
        float cl = 0.f, dm = 0.f, ot = 0.f;
        if (lane < BATCH) {
            int craw = cell_area[0];
            // robust to int32 or float32 encoding of the scalar (both yield 1.0 here)
            float ca = (craw >= 1 && craw <= 1000000) ? (float)craw : __int_as_float(craw);
            float pc = fmaxf(g_sums[0][lane] / ca, 0.f);
            float d = fabsf(pc - (float)gt_counts[lane]);
            cl = (d < 10.f) ? (0.5f * d * d / 10.f) : (d - 5.f);
#pragma unroll
            for (int c = 0; c < 8; ++c) dm += g_dmpart[lane][c];
            ot = g_ot_pb[lane];
        }
#pragma unroll
        for (int o = 16; o > 0; o >>= 1) {
            cl += __shfl_down_sync(M, cl, o);
            dm += __shfl_down_sync(M, dm, o);
            ot += __shfl_down_sync(M, ot, o);
        }
        if (lane == 0) {
            out[0] = 3.0f * (cl * (1.f / 16.f)) + 0.5f * (dm * (1.f / 16.f)) +
                     0.3f * (ot * (1.f / 16.f));
        }
    }
}

// ---------------- launch ----------------
extern "C" void kernel_launch(void* const* d_in, const int* in_sizes, int n_in,
                              void* d_out, int out_size)
{
    const float* pred = (const float*)d_in[0];
    const float* gt = (const float*)d_in[1];
    const int* counts = (const int*)d_in[2];
    const int* cell = (const int*)d_in[3];
    float* out = (float*)d_out;

    k_front<<<dim3(16, 32), 256>>>(pred, gt);
    k_convv<<<dim3(4, 32), 256>>>();
    k_back<<<NBLK3, 1024>>>(counts, cell, out);
}